// round 2
// baseline (speedup 1.0000x reference)
#include <cuda_runtime.h>
#include <cuda_bf16.h>
#include <cstdint>

// ============================================================================
// Problem constants
// ============================================================================
#define B_ROWS 32768
#define D_INF  512
#define D_OUTF 2048
#define VBSZ   256
#define NVB    (B_ROWS / VBSZ)   // 128
#define BN_EPS 1e-5f

// ============================================================================
// Device scratch (static globals; no cudaMalloc allowed)
// ============================================================================
__device__ __nv_bfloat16 g_A0[(size_t)B_ROWS * D_INF];   // hi bf16 of feat
__device__ __nv_bfloat16 g_A1[(size_t)B_ROWS * D_INF];   // lo bf16 of feat
__device__ __nv_bfloat16 g_W0[(size_t)D_OUTF * D_INF];   // hi bf16 of W
__device__ __nv_bfloat16 g_W1[(size_t)D_OUTF * D_INF];   // lo bf16 of W
__device__ float         g_x [(size_t)B_ROWS * D_OUTF];  // GEMM result
__device__ float         g_scale[(size_t)NVB * D_OUTF];  // rstd*gamma
__device__ float         g_shift[(size_t)NVB * D_OUTF];  // beta - mean*rstd*gamma

// ============================================================================
// PTX helpers (base ISA only: cp.async + ldmatrix + mma.sync, all sm_80/75+)
// ============================================================================
__device__ __forceinline__ uint32_t smem_to_u32(const void* p) {
    uint32_t a;
    asm("{ .reg .u64 t; cvta.to.shared.u64 t, %1; cvt.u32.u64 %0, t; }" : "=r"(a) : "l"(p));
    return a;
}

#define CP_ASYNC_16(dst_u32, src_ptr) \
    asm volatile("cp.async.cg.shared.global [%0], [%1], 16;" :: "r"(dst_u32), "l"(src_ptr))
#define CP_ASYNC_COMMIT() asm volatile("cp.async.commit_group;" ::: "memory")
#define CP_ASYNC_WAIT_1() asm volatile("cp.async.wait_group 1;" ::: "memory")

#define LDMATRIX_X4(r0, r1, r2, r3, addr) \
    asm volatile("ldmatrix.sync.aligned.m8n8.x4.shared.b16 {%0,%1,%2,%3}, [%4];" \
                 : "=r"(r0), "=r"(r1), "=r"(r2), "=r"(r3) : "r"(addr))

#define MMA_16816(d, a, b0, b1) \
    asm volatile("mma.sync.aligned.m16n8k16.row.col.f32.bf16.bf16.f32 " \
                 "{%0,%1,%2,%3}, {%4,%5,%6,%7}, {%8,%9}, {%0,%1,%2,%3};" \
                 : "+f"((d)[0]), "+f"((d)[1]), "+f"((d)[2]), "+f"((d)[3]) \
                 : "r"((a)[0]), "r"((a)[1]), "r"((a)[2]), "r"((a)[3]), "r"(b0), "r"(b1))

// ============================================================================
// Kernel 1: split fp32 -> (bf16 hi, bf16 lo) for A (feat) and W
// ============================================================================
__global__ void k_split(const float* __restrict__ feat, const float* __restrict__ Wm) {
    constexpr int NA4 = B_ROWS * D_INF / 4;   // 4194304
    constexpr int NW4 = D_OUTF * D_INF / 4;   // 262144
    int idx = blockIdx.x * blockDim.x + threadIdx.x;
    const float* src;
    __nv_bfloat16 *d0, *d1;
    int i;
    if (idx < NA4) { src = feat; d0 = g_A0; d1 = g_A1; i = idx; }
    else if (idx < NA4 + NW4) { src = Wm; d0 = g_W0; d1 = g_W1; i = idx - NA4; }
    else return;

    float4 a = reinterpret_cast<const float4*>(src)[i];
    __nv_bfloat16 hx = __float2bfloat16(a.x), hy = __float2bfloat16(a.y);
    __nv_bfloat16 hz = __float2bfloat16(a.z), hw = __float2bfloat16(a.w);
    __nv_bfloat16 lx = __float2bfloat16(a.x - __bfloat162float(hx));
    __nv_bfloat16 ly = __float2bfloat16(a.y - __bfloat162float(hy));
    __nv_bfloat16 lz = __float2bfloat16(a.z - __bfloat162float(hz));
    __nv_bfloat16 lw = __float2bfloat16(a.w - __bfloat162float(hw));

    __nv_bfloat162 h01 = __nv_bfloat162(hx, hy), h23 = __nv_bfloat162(hz, hw);
    __nv_bfloat162 l01 = __nv_bfloat162(lx, ly), l23 = __nv_bfloat162(lz, lw);
    uint2 hv, lv;
    hv.x = *reinterpret_cast<uint32_t*>(&h01); hv.y = *reinterpret_cast<uint32_t*>(&h23);
    lv.x = *reinterpret_cast<uint32_t*>(&l01); lv.y = *reinterpret_cast<uint32_t*>(&l23);
    *reinterpret_cast<uint2*>(d0 + (size_t)i * 4) = hv;
    *reinterpret_cast<uint2*>(d1 + (size_t)i * 4) = lv;
}

// ============================================================================
// Kernel 2: GEMM x = A @ W^T via mma.sync bf16, 2-term split (3 MMAs/k-step)
//   CTA 128x128, BK=32, 3-stage cp.async pipeline, 8 warps (2m x 4n), warp
//   tile 64x32. SMEM rows padded to 40 bf16 (80B) -> ldmatrix conflict-free.
// ============================================================================
#define BK        32
#define ROW_PAD   40                       // bf16 per smem row (80 bytes)
#define TILE_B    (128 * ROW_PAD * 2)      // 10240 bytes per 128x32 tile
#define STAGE_B   (4 * TILE_B)             // A0,A1,W0,W1 = 40960 bytes
#define NSTAGE    3
#define GEMM_SMEM (NSTAGE * STAGE_B)       // 122880 bytes
#define KTILES    (D_INF / BK)             // 16

// Issue one stage of cp.async loads: 4 tiles x 128 rows x 4 x 16B chunks.
__device__ __forceinline__ void gemm_load_stage(
    uint32_t smem_base, int stage, int m0, int n0, int k0, int tid)
{
    const __nv_bfloat16* bases[4] = {
        g_A0 + (size_t)m0 * D_INF + k0,
        g_A1 + (size_t)m0 * D_INF + k0,
        g_W0 + (size_t)n0 * D_INF + k0,
        g_W1 + (size_t)n0 * D_INF + k0
    };
    uint32_t sbase = smem_base + stage * STAGE_B;
#pragma unroll
    for (int i = 0; i < 8; i++) {
        int chunk = tid + 256 * i;          // 0..2047
        int tile = chunk >> 9;              // 0..3
        int idx = chunk & 511;
        int row = idx >> 2;
        int seg = idx & 3;
        const __nv_bfloat16* src = bases[tile] + (size_t)row * D_INF + seg * 8;
        uint32_t dst = sbase + tile * TILE_B + row * (ROW_PAD * 2) + seg * 16;
        CP_ASYNC_16(dst, src);
    }
}

__global__ void __launch_bounds__(256, 1) k_gemm() {
    extern __shared__ char smem[];
    const uint32_t smem_base = smem_to_u32(smem);
    const int tid = threadIdx.x;
    const int wid = tid >> 5, lid = tid & 31;
    const int m0 = blockIdx.y * 128;
    const int n0 = blockIdx.x * 128;
    const int wm = wid & 1;                 // 0..1 -> m offset 64*wm
    const int wn = wid >> 1;                // 0..3 -> n offset 32*wn

    // Per-lane ldmatrix byte offsets (within a stage).
    // A (tiles 0/1): row = wm*64 + mf*16 + (lid & 15); khalf = lid >> 4
    uint32_t offA[4];
#pragma unroll
    for (int mf = 0; mf < 4; mf++)
        offA[mf] = (uint32_t)((wm * 64 + mf * 16 + (lid & 15)) * (ROW_PAD * 2)
                              + (lid >> 4) * 16);
    // W (tiles 2/3): row = wn*32 + g*16 + (lid & 7) + ((lid >> 4) << 3); khalf = (lid>>3)&1
    uint32_t offB[2];
#pragma unroll
    for (int g = 0; g < 2; g++)
        offB[g] = (uint32_t)((wn * 32 + g * 16 + (lid & 7) + ((lid >> 4) << 3)) * (ROW_PAD * 2)
                             + ((lid >> 3) & 1) * 16);

    float acc[4][4][4];
#pragma unroll
    for (int mf = 0; mf < 4; mf++)
#pragma unroll
        for (int nf = 0; nf < 4; nf++)
#pragma unroll
            for (int r = 0; r < 4; r++) acc[mf][nf][r] = 0.f;

    // Prologue: stages 0,1
    gemm_load_stage(smem_base, 0, m0, n0, 0, tid);
    CP_ASYNC_COMMIT();
    gemm_load_stage(smem_base, 1, m0, n0, BK, tid);
    CP_ASYNC_COMMIT();

    for (int kt = 0; kt < KTILES; kt++) {
        CP_ASYNC_WAIT_1();
        __syncthreads();

        if (kt + 2 < KTILES)
            gemm_load_stage(smem_base, (kt + 2) % NSTAGE, m0, n0, (kt + 2) * BK, tid);
        CP_ASYNC_COMMIT();

        uint32_t sbase = smem_base + (kt % NSTAGE) * STAGE_B;
        uint32_t sA0 = sbase, sA1 = sbase + TILE_B;
        uint32_t sW0 = sbase + 2 * TILE_B, sW1 = sbase + 3 * TILE_B;

#pragma unroll
        for (int kk = 0; kk < 2; kk++) {    // two k16 steps inside BK=32
            uint32_t koff = kk * 32;        // 16 bf16 = 32 bytes

            uint32_t a0[4][4], a1[4][4];
#pragma unroll
            for (int mf = 0; mf < 4; mf++) {
                LDMATRIX_X4(a0[mf][0], a0[mf][1], a0[mf][2], a0[mf][3], sA0 + offA[mf] + koff);
                LDMATRIX_X4(a1[mf][0], a1[mf][1], a1[mf][2], a1[mf][3], sA1 + offA[mf] + koff);
            }
            uint32_t b0[2][4], b1[2][4];    // [g][matrix]; nf=2g -> regs 0,1; nf=2g+1 -> 2,3
#pragma unroll
            for (int g = 0; g < 2; g++) {
                LDMATRIX_X4(b0[g][0], b0[g][1], b0[g][2], b0[g][3], sW0 + offB[g] + koff);
                LDMATRIX_X4(b1[g][0], b1[g][1], b1[g][2], b1[g][3], sW1 + offB[g] + koff);
            }
#pragma unroll
            for (int mf = 0; mf < 4; mf++) {
#pragma unroll
                for (int nf = 0; nf < 4; nf++) {
                    int g = nf >> 1, p = (nf & 1) * 2;
                    MMA_16816(acc[mf][nf], a0[mf], b0[g][p], b0[g][p + 1]);
                    MMA_16816(acc[mf][nf], a0[mf], b1[g][p], b1[g][p + 1]);
                    MMA_16816(acc[mf][nf], a1[mf], b0[g][p], b0[g][p + 1]);
                }
            }
        }
        __syncthreads();
    }

    // Epilogue: write fp32 result tile to g_x
    const int rbase = m0 + wm * 64 + (lid >> 2);
    const int cbase = n0 + wn * 32 + (lid & 3) * 2;
#pragma unroll
    for (int mf = 0; mf < 4; mf++) {
#pragma unroll
        for (int nf = 0; nf < 4; nf++) {
            int r0 = rbase + mf * 16;
            int c = cbase + nf * 8;
            float2 v0 = make_float2(acc[mf][nf][0], acc[mf][nf][1]);
            float2 v1 = make_float2(acc[mf][nf][2], acc[mf][nf][3]);
            *reinterpret_cast<float2*>(g_x + (size_t)r0 * D_OUTF + c) = v0;
            *reinterpret_cast<float2*>(g_x + (size_t)(r0 + 8) * D_OUTF + c) = v1;
        }
    }
}

// ============================================================================
// Kernel 3: GhostBN stats -> folded scale/shift per (vb, d)
// ============================================================================
__global__ void k_stats(const float* __restrict__ gamma, const float* __restrict__ beta) {
    int d = blockIdx.x * 256 + threadIdx.x;
    int vb = blockIdx.y;
    const float* p = g_x + (size_t)vb * VBSZ * D_OUTF + d;
    float s = 0.f, s2 = 0.f;
#pragma unroll 8
    for (int r = 0; r < VBSZ; r++) {
        float v = p[(size_t)r * D_OUTF];
        s += v;
        s2 = fmaf(v, v, s2);
    }
    float mean = s * (1.f / VBSZ);
    float var = fmaxf(s2 * (1.f / VBSZ) - mean * mean, 0.f);
    float rstd = rsqrtf(var + BN_EPS);
    float sc = rstd * gamma[d];
    g_scale[(size_t)vb * D_OUTF + d] = sc;
    g_shift[(size_t)vb * D_OUTF + d] = beta[d] - mean * sc;
}

// ============================================================================
// Kernel 4: fused BN*prior + sparsemax, one warp per row (D=2048 -> 64/lane)
//   tau by bisection in [max-1, max] then 2 exact fixed-point polish steps.
// ============================================================================
__global__ void __launch_bounds__(256) k_sparsemax(const float* __restrict__ priors,
                                                   float* __restrict__ out) {
    const int wid = threadIdx.x >> 5, lid = threadIdx.x & 31;
    const int row = blockIdx.x * 8 + wid;
    const int vb = row >> 8;

    const float4* xv = reinterpret_cast<const float4*>(g_x + (size_t)row * D_OUTF);
    const float4* pv = reinterpret_cast<const float4*>(priors + (size_t)row * D_OUTF);
    const float4* sv = reinterpret_cast<const float4*>(g_scale + (size_t)vb * D_OUTF);
    const float4* hv = reinterpret_cast<const float4*>(g_shift + (size_t)vb * D_OUTF);

    float z[64];
#pragma unroll
    for (int j = 0; j < 16; j++) {
        int c = lid + 32 * j;
        float4 x = xv[c], p = pv[c], sc = sv[c], sh = hv[c];
        z[4 * j + 0] = fmaf(x.x, sc.x, sh.x) * p.x;
        z[4 * j + 1] = fmaf(x.y, sc.y, sh.y) * p.y;
        z[4 * j + 2] = fmaf(x.z, sc.z, sh.z) * p.z;
        z[4 * j + 3] = fmaf(x.w, sc.w, sh.w) * p.w;
    }

    float m = z[0];
#pragma unroll
    for (int i = 1; i < 64; i++) m = fmaxf(m, z[i]);
#pragma unroll
    for (int o = 16; o; o >>= 1) m = fmaxf(m, __shfl_xor_sync(0xffffffffu, m, o));

    float lo = m - 1.f, hi = m;
    for (int it = 0; it < 22; it++) {
        float mid = 0.5f * (lo + hi);
        float s = 0.f;
#pragma unroll
        for (int i = 0; i < 64; i++) s += fmaxf(z[i] - mid, 0.f);
#pragma unroll
        for (int o = 16; o; o >>= 1) s += __shfl_xor_sync(0xffffffffu, s, o);
        if (s > 1.f) lo = mid; else hi = mid;
    }
    float tau = 0.5f * (lo + hi);
#pragma unroll
    for (int pp = 0; pp < 2; pp++) {
        float S = 0.f, C = 0.f;
#pragma unroll
        for (int i = 0; i < 64; i++) {
            if (z[i] > tau) { S += z[i]; C += 1.f; }
        }
#pragma unroll
        for (int o = 16; o; o >>= 1) {
            S += __shfl_xor_sync(0xffffffffu, S, o);
            C += __shfl_xor_sync(0xffffffffu, C, o);
        }
        tau = (S - 1.f) / C;
    }

    float4* ov = reinterpret_cast<float4*>(out + (size_t)row * D_OUTF);
#pragma unroll
    for (int j = 0; j < 16; j++) {
        int c = lid + 32 * j;
        float4 v;
        v.x = fmaxf(z[4 * j + 0] - tau, 0.f);
        v.y = fmaxf(z[4 * j + 1] - tau, 0.f);
        v.z = fmaxf(z[4 * j + 2] - tau, 0.f);
        v.w = fmaxf(z[4 * j + 3] - tau, 0.f);
        ov[c] = v;
    }
}

// ============================================================================
// Launch
// ============================================================================
extern "C" void kernel_launch(void* const* d_in, const int* in_sizes, int n_in,
                              void* d_out, int out_size) {
    const float* priors = (const float*)d_in[0];   // [32768, 2048]
    const float* feat   = (const float*)d_in[1];   // [32768, 512]
    const float* Wm     = (const float*)d_in[2];   // [2048, 512]
    const float* gamma  = (const float*)d_in[3];   // [2048]
    const float* beta   = (const float*)d_in[4];   // [2048]
    float* out = (float*)d_out;

    static bool attr_set = false;
    if (!attr_set) {
        cudaFuncSetAttribute(k_gemm, cudaFuncAttributeMaxDynamicSharedMemorySize, GEMM_SMEM);
        attr_set = true;
    }

    // split fp32 -> bf16 hi/lo:  (NA4 + NW4) / 256 = 17408 blocks exactly
    k_split<<<17408, 256>>>(feat, Wm);
    // GEMM: grid.x = N tiles (16), grid.y = M tiles (256); x-fastest shares A tile
    k_gemm<<<dim3(16, 256), 256, GEMM_SMEM>>>();
    // GhostBN stats
    k_stats<<<dim3(D_OUTF / 256, NVB), 256>>>(gamma, beta);
    // fused BN * prior + sparsemax, warp per row
    k_sparsemax<<<B_ROWS / 8, 256>>>(priors, out);
}